// round 3
// baseline (speedup 1.0000x reference)
#include <cuda_runtime.h>
#include <cuda_bf16.h>
#include <math.h>
#include <stdint.h>

// Fixed problem shape: B=2048, S=1, E=1024, H=128, DK=NW=8.
#define M_DIM 2048
#define E_DIM 1024

#define BM 128
#define BN 128
#define BK 32
#define NKITER (E_DIM / BK)

// -------- device scratch (no cudaMalloc allowed) --------
__device__ __nv_bfloat16 g_xh[M_DIM * E_DIM];
__device__ __nv_bfloat16 g_xl[M_DIM * E_DIM];
__device__ __nv_bfloat16 g_wvh[E_DIM * E_DIM];
__device__ __nv_bfloat16 g_wvl[E_DIM * E_DIM];
__device__ __nv_bfloat16 g_wch[E_DIM * E_DIM];
__device__ __nv_bfloat16 g_wcl[E_DIM * E_DIM];
__device__ __nv_bfloat16 g_qh[M_DIM * E_DIM];
__device__ __nv_bfloat16 g_ql[M_DIM * E_DIM];

// -------- helpers --------
__device__ __forceinline__ void split_bf(float x, __nv_bfloat16& h, __nv_bfloat16& l) {
    h = __float2bfloat16(x);
    l = __float2bfloat16(x - __bfloat162float(h));
}

struct alignas(8) bf4 { __nv_bfloat16 a, b, c, d; };

#define CP_ASYNC16(dst, src) \
    asm volatile("cp.async.cg.shared.global [%0], [%1], 16;\n" :: "r"(dst), "l"(src))

#define LDSM4(r, addr) \
    asm volatile("ldmatrix.sync.aligned.m8n8.x4.shared.b16 {%0,%1,%2,%3}, [%4];" \
        : "=r"((r)[0]), "=r"((r)[1]), "=r"((r)[2]), "=r"((r)[3]) : "r"(addr))

__device__ __forceinline__ void mma_bf16(float* d, const uint32_t* a, const uint32_t* b) {
    asm volatile(
        "mma.sync.aligned.m16n8k16.row.col.f32.bf16.bf16.f32 "
        "{%0,%1,%2,%3}, {%4,%5,%6,%7}, {%8,%9}, {%0,%1,%2,%3};\n"
        : "+f"(d[0]), "+f"(d[1]), "+f"(d[2]), "+f"(d[3])
        : "r"(a[0]), "r"(a[1]), "r"(a[2]), "r"(a[3]), "r"(b[0]), "r"(b[1]));
}

// -------- fp32 -> (hi, lo) bf16 split, vectorized --------
__global__ void split_kernel(const float* __restrict__ src,
                             __nv_bfloat16* __restrict__ hi,
                             __nv_bfloat16* __restrict__ lo, int n4)
{
    int i = blockIdx.x * blockDim.x + threadIdx.x;
    if (i >= n4) return;
    float4 v = reinterpret_cast<const float4*>(src)[i];
    bf4 h4, l4;
    split_bf(v.x, h4.a, l4.a);
    split_bf(v.y, h4.b, l4.b);
    split_bf(v.z, h4.c, l4.c);
    split_bf(v.w, h4.d, l4.d);
    reinterpret_cast<bf4*>(hi)[i] = h4;
    reinterpret_cast<bf4*>(lo)[i] = l4;
}

// -------- GEMM: C[M,N] = A[M,K] @ B[N,K]^T, 3xBF16 split --------
// FUSE_Q=true : epilogue applies closed-form quantum layer and writes (qh,ql) bf16
// FUSE_Q=false: epilogue adds bias and writes float C
template <bool FUSE_Q>
__global__ void __launch_bounds__(256, 1)
gemm_bf16x3(const __nv_bfloat16* __restrict__ Ah, const __nv_bfloat16* __restrict__ Al,
            const __nv_bfloat16* __restrict__ Bh, const __nv_bfloat16* __restrict__ Bl,
            const float* __restrict__ bias, float* __restrict__ C,
            __nv_bfloat16* __restrict__ Qh, __nv_bfloat16* __restrict__ Ql,
            const float* __restrict__ rx)
{
    extern __shared__ char smem[];
    const uint32_t sbase = (uint32_t)__cvta_generic_to_shared(smem);

    const int tid  = threadIdx.x;
    const int lane = tid & 31;
    const int warp = tid >> 5;
    const int bm0 = blockIdx.y * BM;
    const int bn0 = blockIdx.x * BN;
    const int wm = (warp & 1) * 64;    // 2 warps along M, warp tile 64
    const int wn = (warp >> 1) * 32;   // 4 warps along N, warp tile 32

    // ---- cp.async per-thread offsets ----
    const int r0 = tid >> 2;           // 0..63
    const int c  = tid & 3;            // 16B chunk
    const uint32_t sw = (uint32_t)(c ^ ((r0 >> 1) & 3));
    const uint32_t sd0 = (uint32_t)r0 * 64 + sw * 16;
    const size_t gA0 = (size_t)(bm0 + r0) * E_DIM + c * 8;
    const size_t gB0 = (size_t)(bn0 + r0) * E_DIM + c * 8;

    // ---- ldmatrix per-thread addresses (buf 0, ks 0) ----
    const int arow = ((lane >> 3) & 1) * 8 + (lane & 7);
    const int achk = (lane >> 4) & 1;
    uint32_t addrA[2][4];   // [split][mt]
#pragma unroll
    for (int mt = 0; mt < 4; mt++) {
        int rA = wm + mt * 16 + arow;
        uint32_t off = (uint32_t)rA * 64 + (uint32_t)((achk ^ ((rA >> 1) & 3)) * 16);
#pragma unroll
        for (int s = 0; s < 2; s++)
            addrA[s][mt] = sbase + (uint32_t)s * 8192 + off;
    }
    const int brow = ((lane >> 4) & 1) * 8 + (lane & 7);
    const int bchk = (lane >> 3) & 1;
    uint32_t addrB[2][2];   // [split][pair]
#pragma unroll
    for (int p = 0; p < 2; p++) {
        int rB = wn + p * 16 + brow;
        uint32_t off = (uint32_t)rB * 64 + (uint32_t)((bchk ^ ((rB >> 1) & 3)) * 16);
#pragma unroll
        for (int s = 0; s < 2; s++)
            addrB[s][p] = sbase + 32768u + (uint32_t)s * 8192 + off;
    }

    float acc[4][4][4];
#pragma unroll
    for (int mt = 0; mt < 4; mt++)
#pragma unroll
        for (int nt = 0; nt < 4; nt++)
#pragma unroll
            for (int i = 0; i < 4; i++) acc[mt][nt][i] = 0.0f;

    auto load_tile = [&](int buf, int kt) {
        uint32_t aB = sbase + (uint32_t)buf * 16384;
        uint32_t bB = aB + 32768u;
        CP_ASYNC16(aB + sd0,               Ah + gA0 + kt);
        CP_ASYNC16(aB + sd0 + 4096,        Ah + gA0 + 64 * E_DIM + kt);
        CP_ASYNC16(aB + 8192 + sd0,        Al + gA0 + kt);
        CP_ASYNC16(aB + 8192 + sd0 + 4096, Al + gA0 + 64 * E_DIM + kt);
        CP_ASYNC16(bB + sd0,               Bh + gB0 + kt);
        CP_ASYNC16(bB + sd0 + 4096,        Bh + gB0 + 64 * E_DIM + kt);
        CP_ASYNC16(bB + 8192 + sd0,        Bl + gB0 + kt);
        CP_ASYNC16(bB + 8192 + sd0 + 4096, Bl + gB0 + 64 * E_DIM + kt);
        asm volatile("cp.async.commit_group;\n");
    };

    load_tile(0, 0);

    for (int it = 0; it < NKITER; it++) {
        if (it + 1 < NKITER) {
            load_tile((it + 1) & 1, (it + 1) * BK);
            asm volatile("cp.async.wait_group 1;\n");
        } else {
            asm volatile("cp.async.wait_group 0;\n");
        }
        __syncthreads();

        const uint32_t bufoff = (uint32_t)(it & 1) * 16384;
#pragma unroll
        for (int ks = 0; ks < 2; ks++) {
            const uint32_t kx = (uint32_t)ks << 5;
            uint32_t a_hi[4][4], a_lo[4][4];
#pragma unroll
            for (int mt = 0; mt < 4; mt++) {
                LDSM4(a_hi[mt], (addrA[0][mt] + bufoff) ^ kx);
                LDSM4(a_lo[mt], (addrA[1][mt] + bufoff) ^ kx);
            }
            uint32_t b_hi[2][4], b_lo[2][4];
#pragma unroll
            for (int p = 0; p < 2; p++) {
                LDSM4(b_hi[p], (addrB[0][p] + bufoff) ^ kx);
                LDSM4(b_lo[p], (addrB[1][p] + bufoff) ^ kx);
            }
            // Three sweeps; within each sweep all 16 accumulators are
            // independent -> accumulator reuse distance = 16 HMMAs.
#pragma unroll
            for (int mt = 0; mt < 4; mt++)
#pragma unroll
                for (int p = 0; p < 2; p++) {
                    mma_bf16(acc[mt][2 * p],     a_hi[mt], &b_hi[p][0]);
                    mma_bf16(acc[mt][2 * p + 1], a_hi[mt], &b_hi[p][2]);
                }
#pragma unroll
            for (int mt = 0; mt < 4; mt++)
#pragma unroll
                for (int p = 0; p < 2; p++) {
                    mma_bf16(acc[mt][2 * p],     a_hi[mt], &b_lo[p][0]);
                    mma_bf16(acc[mt][2 * p + 1], a_hi[mt], &b_lo[p][2]);
                }
#pragma unroll
            for (int mt = 0; mt < 4; mt++)
#pragma unroll
                for (int p = 0; p < 2; p++) {
                    mma_bf16(acc[mt][2 * p],     a_lo[mt], &b_hi[p][0]);
                    mma_bf16(acc[mt][2 * p + 1], a_lo[mt], &b_hi[p][2]);
                }
        }
        __syncthreads();
    }

    // ---- epilogue ----
    const int gp = lane >> 2, tg = lane & 3;

    if (!FUSE_Q) {
#pragma unroll
        for (int nt = 0; nt < 4; nt++) {
            const int n = bn0 + wn + nt * 8 + tg * 2;
            const float b0 = bias[n], b1 = bias[n + 1];
#pragma unroll
            for (int mt = 0; mt < 4; mt++) {
                const int m = bm0 + wm + mt * 16 + gp;
                float2 o0 = make_float2(acc[mt][nt][0] + b0, acc[mt][nt][1] + b1);
                float2 o1 = make_float2(acc[mt][nt][2] + b0, acc[mt][nt][3] + b1);
                *reinterpret_cast<float2*>(C + (size_t)m * E_DIM + n) = o0;
                *reinterpret_cast<float2*>(C + (size_t)(m + 8) * E_DIM + n) = o1;
            }
        }
    } else {
        // Quantum closed form. Each quad (tg=0..3, consecutive lanes) holds one
        // 8-wire group per (mt, nt, row-half): thread tg owns wires 2tg, 2tg+1.
        //   c_j = cos(v_j + rx_j);  q[w] = c0..cw (w>=1);  q[0] = c1..c7
        const float rxe = rx[tg * 2], rxo = rx[tg * 2 + 1];
#pragma unroll
        for (int nt = 0; nt < 4; nt++) {
            const int n = bn0 + wn + nt * 8 + tg * 2;
#pragma unroll
            for (int mt = 0; mt < 4; mt++) {
#pragma unroll
                for (int h2 = 0; h2 < 2; h2++) {
                    const float va = acc[mt][nt][2 * h2];
                    const float vb = acc[mt][nt][2 * h2 + 1];
                    const float c0 = __cosf(va + rxe);
                    const float c1 = __cosf(vb + rxo);
                    const float d  = c0 * c1;
                    // inclusive scan of pair-products across the quad
                    float s = d;
                    float u = __shfl_up_sync(0xffffffffu, s, 1, 4); if (tg >= 1) s *= u;
                    u = __shfl_up_sync(0xffffffffu, s, 2, 4);       if (tg >= 2) s *= u;
                    const float excl = __shfl_up_sync(0xffffffffu, s, 1, 4);
                    const float d1v = __shfl_sync(0xffffffffu, d, 1, 4);
                    const float d2v = __shfl_sync(0xffffffffu, d, 2, 4);
                    const float d3v = __shfl_sync(0xffffffffu, d, 3, 4);
                    float pe, po;
                    if (tg == 0) {
                        pe = c1 * d1v * d2v * d3v;  // wire0: c1*(c2c3)(c4c5)(c6c7)
                        po = d;                      // wire1: c0*c1
                    } else {
                        pe = excl * c0;              // wire 2tg
                        po = s;                      // wire 2tg+1
                    }
                    const int m = bm0 + wm + mt * 16 + gp + h2 * 8;
                    __nv_bfloat16 he, le, ho, lo2;
                    split_bf(pe, he, le);
                    split_bf(po, ho, lo2);
                    __nv_bfloat162 H; H.x = he; H.y = ho;
                    __nv_bfloat162 L; L.x = le; L.y = lo2;
                    *reinterpret_cast<__nv_bfloat162*>(Qh + (size_t)m * E_DIM + n) = H;
                    *reinterpret_cast<__nv_bfloat162*>(Ql + (size_t)m * E_DIM + n) = L;
                }
            }
        }
    }
}

extern "C" void kernel_launch(void* const* d_in, const int* in_sizes, int n_in,
                              void* d_out, int out_size)
{
    const float* x  = (const float*)d_in[0];
    // d_in[1]=wq, d_in[2]=wk unused: S==1 -> softmax==1 -> attention out == v
    const float* wv = (const float*)d_in[3];
    const float* wc = (const float*)d_in[4];
    const float* bc = (const float*)d_in[5];
    const float* rx = (const float*)d_in[6];
    float* out = (float*)d_out;

    __nv_bfloat16 *xh, *xl, *wvh, *wvl, *wch, *wcl, *qh, *ql;
    cudaGetSymbolAddress((void**)&xh,  g_xh);
    cudaGetSymbolAddress((void**)&xl,  g_xl);
    cudaGetSymbolAddress((void**)&wvh, g_wvh);
    cudaGetSymbolAddress((void**)&wvl, g_wvl);
    cudaGetSymbolAddress((void**)&wch, g_wch);
    cudaGetSymbolAddress((void**)&wcl, g_wcl);
    cudaGetSymbolAddress((void**)&qh,  g_qh);
    cudaGetSymbolAddress((void**)&ql,  g_ql);

    cudaFuncSetAttribute(gemm_bf16x3<true>,  cudaFuncAttributeMaxDynamicSharedMemorySize, 65536);
    cudaFuncSetAttribute(gemm_bf16x3<false>, cudaFuncAttributeMaxDynamicSharedMemorySize, 65536);

    // split inputs into bf16 hi/lo
    split_kernel<<<(M_DIM * E_DIM / 4 + 255) / 256, 256>>>(x, xh, xl, M_DIM * E_DIM / 4);
    split_kernel<<<(E_DIM * E_DIM / 4 + 255) / 256, 256>>>(wv, wvh, wvl, E_DIM * E_DIM / 4);
    split_kernel<<<(E_DIM * E_DIM / 4 + 255) / 256, 256>>>(wc, wch, wcl, E_DIM * E_DIM / 4);

    dim3 grid(E_DIM / BN, M_DIM / BM);
    // GEMM1 (v = x @ wv^T) with fused quantum epilogue -> (qh, ql)
    gemm_bf16x3<true><<<grid, 256, 65536>>>(xh, xl, wvh, wvl, nullptr, nullptr, qh, ql, rx);
    // GEMM2: out = q @ wc^T + bc
    gemm_bf16x3<false><<<grid, 256, 65536>>>(qh, ql, wch, wcl, bc, out, nullptr, nullptr, nullptr);
}

// round 5
// speedup vs baseline: 1.0245x; 1.0245x over previous
#include <cuda_runtime.h>
#include <cuda_bf16.h>
#include <math.h>
#include <stdint.h>

// Fixed problem shape: B=2048, S=1, E=1024, H=128, DK=NW=8.
#define M_DIM 2048
#define E_DIM 1024

#define BM 128
#define BN 128
#define BK 32
#define NKIT (E_DIM / BK)      // 32
#define STAGES 3
#define STAGE_BYTES 32768      // Ah(8K) Al(8K) Bh(8K) Bl(8K)
#define SMEM_TOTAL (STAGES * STAGE_BYTES)  // 98304

// -------- device scratch (no cudaMalloc allowed) --------
__device__ __nv_bfloat16 g_xh[M_DIM * E_DIM];
__device__ __nv_bfloat16 g_xl[M_DIM * E_DIM];
__device__ __nv_bfloat16 g_wvh[E_DIM * E_DIM];
__device__ __nv_bfloat16 g_wvl[E_DIM * E_DIM];
__device__ __nv_bfloat16 g_wch[E_DIM * E_DIM];
__device__ __nv_bfloat16 g_wcl[E_DIM * E_DIM];
__device__ __nv_bfloat16 g_qh[M_DIM * E_DIM];
__device__ __nv_bfloat16 g_ql[M_DIM * E_DIM];

// -------- helpers --------
__device__ __forceinline__ void split_bf(float x, __nv_bfloat16& h, __nv_bfloat16& l) {
    h = __float2bfloat16(x);
    l = __float2bfloat16(x - __bfloat162float(h));
}
struct alignas(8) bf4 { __nv_bfloat16 a, b, c, d; };

#define CP_ASYNC16(dst, src) \
    asm volatile("cp.async.cg.shared.global [%0], [%1], 16;\n" :: "r"(dst), "l"(src))

#define LDSM4(r, addr) \
    asm volatile("ldmatrix.sync.aligned.m8n8.x4.shared.b16 {%0,%1,%2,%3}, [%4];" \
        : "=r"((r)[0]), "=r"((r)[1]), "=r"((r)[2]), "=r"((r)[3]) : "r"(addr))

__device__ __forceinline__ void mma_bf16(float* d, const uint32_t* a, const uint32_t* b) {
    asm volatile(
        "mma.sync.aligned.m16n8k16.row.col.f32.bf16.bf16.f32 "
        "{%0,%1,%2,%3}, {%4,%5,%6,%7}, {%8,%9}, {%0,%1,%2,%3};\n"
        : "+f"(d[0]), "+f"(d[1]), "+f"(d[2]), "+f"(d[3])
        : "r"(a[0]), "r"(a[1]), "r"(a[2]), "r"(a[3]), "r"(b[0]), "r"(b[1]));
}

// -------- fp32 -> (hi, lo) bf16 split, vectorized --------
__global__ void split_kernel(const float* __restrict__ src,
                             __nv_bfloat16* __restrict__ hi,
                             __nv_bfloat16* __restrict__ lo, int n4)
{
    int i = blockIdx.x * blockDim.x + threadIdx.x;
    if (i >= n4) return;
    float4 v = reinterpret_cast<const float4*>(src)[i];
    bf4 h4, l4;
    split_bf(v.x, h4.a, l4.a);
    split_bf(v.y, h4.b, l4.b);
    split_bf(v.z, h4.c, l4.c);
    split_bf(v.w, h4.d, l4.d);
    reinterpret_cast<bf4*>(hi)[i] = h4;
    reinterpret_cast<bf4*>(lo)[i] = l4;
}

// -------- GEMM: C[M,N] = A[M,K] @ B[N,K]^T, 3xBF16 split --------
// 512 threads, 16 warps (4x4), warp tile 32x32, 3-stage cp.async pipeline.
// FUSE_Q=true : epilogue applies closed-form quantum layer -> (Qh,Ql) bf16
// FUSE_Q=false: epilogue adds bias -> float C
template <bool FUSE_Q>
__global__ void __launch_bounds__(512, 1)
gemm_bf16x3(const __nv_bfloat16* __restrict__ Ah, const __nv_bfloat16* __restrict__ Al,
            const __nv_bfloat16* __restrict__ Bh, const __nv_bfloat16* __restrict__ Bl,
            const float* __restrict__ bias, float* __restrict__ C,
            __nv_bfloat16* __restrict__ Qh, __nv_bfloat16* __restrict__ Ql,
            const float* __restrict__ rx)
{
    extern __shared__ char smem[];
    const uint32_t sbase = (uint32_t)__cvta_generic_to_shared(smem);

    const int tid  = threadIdx.x;
    const int lane = tid & 31;
    const int warp = tid >> 5;
    const int bm0 = blockIdx.y * BM;
    const int bn0 = blockIdx.x * BN;
    const int wm = (warp & 3) * 32;    // 4 warps along M
    const int wn = (warp >> 2) * 32;   // 4 warps along N

    // ---- cp.async per-thread mapping: 512 threads cover 128 rows x 4 chunks ----
    const int r  = tid >> 2;           // 0..127
    const int c  = tid & 3;            // 16B chunk within 64B row
    const uint32_t sd = (uint32_t)r * 64 + (uint32_t)((c ^ ((r >> 1) & 3)) * 16);
    const size_t gA = (size_t)(bm0 + r) * E_DIM + c * 8;
    const size_t gB = (size_t)(bn0 + r) * E_DIM + c * 8;

    auto load_stage = [&](int s, int kt) {
        const uint32_t base = sbase + (uint32_t)s * STAGE_BYTES;
        CP_ASYNC16(base + sd,          Ah + gA + kt);
        CP_ASYNC16(base + 8192  + sd,  Al + gA + kt);
        CP_ASYNC16(base + 16384 + sd,  Bh + gB + kt);
        CP_ASYNC16(base + 24576 + sd,  Bl + gB + kt);
        asm volatile("cp.async.commit_group;\n");
    };

    // ---- ldmatrix per-thread addresses (stage 0, ks 0) ----
    const int arow = ((lane >> 3) & 1) * 8 + (lane & 7);
    const int achk = (lane >> 4) & 1;
    uint32_t addrA[2][2];   // [split][mt]
#pragma unroll
    for (int mt = 0; mt < 2; mt++) {
        int rA = wm + mt * 16 + arow;
        uint32_t off = (uint32_t)rA * 64 + (uint32_t)((achk ^ ((rA >> 1) & 3)) * 16);
        addrA[0][mt] = sbase + off;            // hi at +0
        addrA[1][mt] = sbase + 8192u + off;    // lo at +8192
    }
    const int brow = ((lane >> 4) & 1) * 8 + (lane & 7);
    const int bchk = (lane >> 3) & 1;
    uint32_t addrB[2][2];   // [split][pair]
#pragma unroll
    for (int p = 0; p < 2; p++) {
        int rB = wn + p * 16 + brow;
        uint32_t off = (uint32_t)rB * 64 + (uint32_t)((bchk ^ ((rB >> 1) & 3)) * 16);
        addrB[0][p] = sbase + 16384u + off;
        addrB[1][p] = sbase + 24576u + off;
    }

    float acc[2][4][4];
#pragma unroll
    for (int mt = 0; mt < 2; mt++)
#pragma unroll
        for (int nt = 0; nt < 4; nt++)
#pragma unroll
            for (int i = 0; i < 4; i++) acc[mt][nt][i] = 0.0f;

    // prologue: stages 0, 1
    load_stage(0, 0);
    load_stage(1, BK);

    for (int it = 0; it < NKIT; it++) {
        if (it < NKIT - 1) asm volatile("cp.async.wait_group 1;\n");
        else               asm volatile("cp.async.wait_group 0;\n");
        __syncthreads();
        if (it + 2 < NKIT) load_stage((it + 2) % STAGES, (it + 2) * BK);

        const uint32_t so = (uint32_t)(it % STAGES) * STAGE_BYTES;
#pragma unroll
        for (int ks = 0; ks < 2; ks++) {
            const uint32_t kx = (uint32_t)ks << 5;
            uint32_t a_hi[2][4], a_lo[2][4], b_hi[2][4], b_lo[2][4];
#pragma unroll
            for (int mt = 0; mt < 2; mt++) {
                LDSM4(a_hi[mt], (addrA[0][mt] + so) ^ kx);
                LDSM4(a_lo[mt], (addrA[1][mt] + so) ^ kx);
            }
#pragma unroll
            for (int p = 0; p < 2; p++) {
                LDSM4(b_hi[p], (addrB[0][p] + so) ^ kx);
                LDSM4(b_lo[p], (addrB[1][p] + so) ^ kx);
            }
#pragma unroll
            for (int mt = 0; mt < 2; mt++)
#pragma unroll
                for (int p = 0; p < 2; p++) {
                    mma_bf16(acc[mt][2 * p],     a_hi[mt], &b_hi[p][0]);
                    mma_bf16(acc[mt][2 * p + 1], a_hi[mt], &b_hi[p][2]);
                    mma_bf16(acc[mt][2 * p],     a_hi[mt], &b_lo[p][0]);
                    mma_bf16(acc[mt][2 * p + 1], a_hi[mt], &b_lo[p][2]);
                    mma_bf16(acc[mt][2 * p],     a_lo[mt], &b_hi[p][0]);
                    mma_bf16(acc[mt][2 * p + 1], a_lo[mt], &b_hi[p][2]);
                }
        }
    }

    // ---- epilogue ----
    const int gp = lane >> 2, tg = lane & 3;

    if (!FUSE_Q) {
#pragma unroll
        for (int nt = 0; nt < 4; nt++) {
            const int n = bn0 + wn + nt * 8 + tg * 2;
            const float b0 = bias[n], b1 = bias[n + 1];
#pragma unroll
            for (int mt = 0; mt < 2; mt++) {
                const int m = bm0 + wm + mt * 16 + gp;
                float2 o0 = make_float2(acc[mt][nt][0] + b0, acc[mt][nt][1] + b1);
                float2 o1 = make_float2(acc[mt][nt][2] + b0, acc[mt][nt][3] + b1);
                *reinterpret_cast<float2*>(C + (size_t)m * E_DIM + n) = o0;
                *reinterpret_cast<float2*>(C + (size_t)(m + 8) * E_DIM + n) = o1;
            }
        }
    } else {
        // Quantum closed form across each quad (lanes tg=0..3 share one 8-wire
        // group per (mt,nt,row-half); thread tg owns wires 2tg, 2tg+1).
        //   c_j = cos(v_j + rx_j);  q[w] = c0..cw (w>=1);  q[0] = c1..c7
        const float rxe = rx[tg * 2], rxo = rx[tg * 2 + 1];
#pragma unroll
        for (int nt = 0; nt < 4; nt++) {
            const int n = bn0 + wn + nt * 8 + tg * 2;
#pragma unroll
            for (int mt = 0; mt < 2; mt++) {
#pragma unroll
                for (int h2 = 0; h2 < 2; h2++) {
                    const float va = acc[mt][nt][2 * h2];
                    const float vb = acc[mt][nt][2 * h2 + 1];
                    const float c0 = __cosf(va + rxe);
                    const float c1 = __cosf(vb + rxo);
                    const float d  = c0 * c1;
                    float s = d;
                    float u = __shfl_up_sync(0xffffffffu, s, 1, 4); if (tg >= 1) s *= u;
                    u = __shfl_up_sync(0xffffffffu, s, 2, 4);       if (tg >= 2) s *= u;
                    const float excl = __shfl_up_sync(0xffffffffu, s, 1, 4);
                    const float d1v = __shfl_sync(0xffffffffu, d, 1, 4);
                    const float d2v = __shfl_sync(0xffffffffu, d, 2, 4);
                    const float d3v = __shfl_sync(0xffffffffu, d, 3, 4);
                    float pe, po;
                    if (tg == 0) {
                        pe = c1 * d1v * d2v * d3v;  // wire0: c1*(c2c3)(c4c5)(c6c7)
                        po = d;                      // wire1: c0*c1
                    } else {
                        pe = excl * c0;              // wire 2tg
                        po = s;                      // wire 2tg+1
                    }
                    const int m = bm0 + wm + mt * 16 + gp + h2 * 8;
                    __nv_bfloat16 he, le, ho, lo2;
                    split_bf(pe, he, le);
                    split_bf(po, ho, lo2);
                    __nv_bfloat162 H; H.x = he; H.y = ho;
                    __nv_bfloat162 L; L.x = le; L.y = lo2;
                    *reinterpret_cast<__nv_bfloat162*>(Qh + (size_t)m * E_DIM + n) = H;
                    *reinterpret_cast<__nv_bfloat162*>(Ql + (size_t)m * E_DIM + n) = L;
                }
            }
        }
    }
}

extern "C" void kernel_launch(void* const* d_in, const int* in_sizes, int n_in,
                              void* d_out, int out_size)
{
    const float* x  = (const float*)d_in[0];
    // d_in[1]=wq, d_in[2]=wk unused: S==1 -> softmax==1 -> attention out == v
    const float* wv = (const float*)d_in[3];
    const float* wc = (const float*)d_in[4];
    const float* bc = (const float*)d_in[5];
    const float* rx = (const float*)d_in[6];
    float* out = (float*)d_out;

    __nv_bfloat16 *xh, *xl, *wvh, *wvl, *wch, *wcl, *qh, *ql;
    cudaGetSymbolAddress((void**)&xh,  g_xh);
    cudaGetSymbolAddress((void**)&xl,  g_xl);
    cudaGetSymbolAddress((void**)&wvh, g_wvh);
    cudaGetSymbolAddress((void**)&wvl, g_wvl);
    cudaGetSymbolAddress((void**)&wch, g_wch);
    cudaGetSymbolAddress((void**)&wcl, g_wcl);
    cudaGetSymbolAddress((void**)&qh,  g_qh);
    cudaGetSymbolAddress((void**)&ql,  g_ql);

    cudaFuncSetAttribute(gemm_bf16x3<true>,  cudaFuncAttributeMaxDynamicSharedMemorySize, SMEM_TOTAL);
    cudaFuncSetAttribute(gemm_bf16x3<false>, cudaFuncAttributeMaxDynamicSharedMemorySize, SMEM_TOTAL);

    // split inputs into bf16 hi/lo
    split_kernel<<<(M_DIM * E_DIM / 4 + 255) / 256, 256>>>(x, xh, xl, M_DIM * E_DIM / 4);
    split_kernel<<<(E_DIM * E_DIM / 4 + 255) / 256, 256>>>(wv, wvh, wvl, E_DIM * E_DIM / 4);
    split_kernel<<<(E_DIM * E_DIM / 4 + 255) / 256, 256>>>(wc, wch, wcl, E_DIM * E_DIM / 4);

    dim3 grid(E_DIM / BN, M_DIM / BM);   // 8 x 16 = 128 CTAs
    // GEMM1 (v = x @ wv^T) with fused quantum epilogue -> (qh, ql)
    gemm_bf16x3<true><<<grid, 512, SMEM_TOTAL>>>(xh, xl, wvh, wvl, nullptr, nullptr, qh, ql, rx);
    // GEMM2: out = q @ wc^T + bc
    gemm_bf16x3<false><<<grid, 512, SMEM_TOTAL>>>(qh, ql, wch, wcl, bc, out, nullptr, nullptr, nullptr);
}